// round 14
// baseline (speedup 1.0000x reference)
#include <cuda_runtime.h>
#include <cuda_fp16.h>
#include <cstdint>

#define BATCH   16
#define NN      400
#define HIDDIM  96
#define DECDIM  64
#define NEDGE   79800
#define NROWS   (BATCH*NN)      /* 6400 */
#define FEATDIM 408
#define EPSF    1e-8f

#define ETD     128             /* edges per CTA tile (4 pair-slabs of 32) */
#define NTILE   624             /* ceil(79800/128) */
#define NWORK   (NTILE*BATCH)   /* 9984 */
#define NCTA_DEC 296            /* 2 CTAs per SM */

/* strides: k=96 A arrays padded to 104 halves (208B rows, conflict-free ldmatrix
   perm 20*g mod 32); k=64 z array 72 halves (144B, perm 4*g). */
#define AKW   52
#define ZKW   36

/* ---- decoder smem byte offsets (total 110336 B -> 2 CTAs/SM) ---- */
#define OF_ABSH 0               /* 128x104 f16 = 26624 */
#define OF_MULH 26624
#define OF_WBH  53248           /* 64x104 f16 = 13312 */
#define OF_WCH  66560
#define OF_W2H  79872           /* 64x72 f16 = 9216 */
#define OF_B1   89088
#define OF_B2   89344
#define OF_W3   89600
#define OF_Z1H  89856           /* 128x72 f16 = 18432 */
#define OF_RED  108288          /* 128x2 f32 = 1024 */
#define OF_EI   109312          /* 128 int */
#define OF_EJ   109824
#define DEC_SMEM 110336

/* -------- scratch (device globals; no runtime allocation allowed) -------- */
__device__ float g_inv[BATCH];
__device__ float g_h1[NROWS*HIDDIM];
__device__ float g_h[NROWS*HIDDIM];
__device__ float g_Pa[NROWS*DECDIM];   /* pair-major transposed: [32][NROWS] float2 */

/* ======================= helpers ======================= */
__device__ __forceinline__ uint32_t smem_u32(const void* p) {
    uint32_t a;
    asm("{ .reg .u64 t; cvta.to.shared.u64 t, %1; cvt.u32.u64 %0, t; }" : "=r"(a) : "l"(p));
    return a;
}
__device__ __forceinline__ uint32_t packh2(float x0, float x1) {
    __half2 hh = __floats2half2_rn(x0, x1);
    return *reinterpret_cast<uint32_t*>(&hh);
}
__device__ __forceinline__ void ldsm4(uint32_t* r, uint32_t a) {
    asm volatile("ldmatrix.sync.aligned.m8n8.x4.shared.b16 {%0,%1,%2,%3}, [%4];"
                 : "=r"(r[0]), "=r"(r[1]), "=r"(r[2]), "=r"(r[3]) : "r"(a));
}
__device__ __forceinline__ void mma_f16(float* c, const uint32_t* a, uint32_t b0, uint32_t b1) {
    asm volatile("mma.sync.aligned.m16n8k16.row.col.f32.f16.f16.f32 "
                 "{%0,%1,%2,%3}, {%4,%5,%6,%7}, {%8,%9}, {%0,%1,%2,%3};"
                 : "+f"(c[0]), "+f"(c[1]), "+f"(c[2]), "+f"(c[3])
                 : "r"(a[0]), "r"(a[1]), "r"(a[2]), "r"(a[3]), "r"(b0), "r"(b1));
}
/* 64-thread pair barrier (named; ids 1..4) */
#define PBAR(id) asm volatile("bar.sync %0, 64;" :: "r"(id) : "memory")

/* ======================= encoder kernels ======================= */
__global__ void reduce_mean_kernel(const float* __restrict__ sc) {
    __shared__ float red[256];
    int b = blockIdx.x;
    const float* p = sc + (size_t)b * NN * NN;
    float s = 0.f;
    for (int i = threadIdx.x; i < NN*NN; i += 256) s += p[i];
    red[threadIdx.x] = s;
    __syncthreads();
    for (int st = 128; st > 0; st >>= 1) {
        if (threadIdx.x < st) red[threadIdx.x] += red[threadIdx.x + st];
        __syncthreads();
    }
    if (threadIdx.x == 0) g_inv[b] = 1.f / fmaxf(red[0] * (1.f/(float)(NN*NN)), EPSF);
}

/* encoder GEMM1 with A generated on the fly (feats never materialized) */
__global__ __launch_bounds__(256) void gemm_enc1_kernel(
    const float* __restrict__ nf, const float* __restrict__ sc,
    const float* __restrict__ smean, const float* __restrict__ sstd,
    const float* __restrict__ W, const float* __restrict__ bias,
    const float* __restrict__ alphap, float* __restrict__ C)
{
    __shared__ float As[8][64];
    __shared__ float Bs[8][64];
    int tid = threadIdx.x;
    int m0 = blockIdx.x * 64, n0 = blockIdx.y * 64;
    int ty = tid >> 4, tx = tid & 15;
    const int K = FEATDIM, N = HIDDIM;
    float acc[4][4] = {};
    for (int k0 = 0; k0 < K; k0 += 8) {
        #pragma unroll
        for (int i = tid; i < 512; i += 256) {
            int m = i >> 3, k = i & 7;
            int row = m0 + m, c = k0 + k;
            float v;
            if (c < 8) v = (nf[row*8 + c] - smean[c]) / (sstd[c] + EPSF);
            else       v = sc[(size_t)row*NN + (c-8)] * g_inv[row / NN];
            As[k][m] = v;
        }
        #pragma unroll
        for (int i = tid; i < 512; i += 256) {
            int k = i >> 6, n = i & 63;
            Bs[k][n] = (n0 + n < N) ? W[(size_t)(k0 + k) * N + (n0 + n)] : 0.f;
        }
        __syncthreads();
        #pragma unroll
        for (int kk = 0; kk < 8; kk++) {
            float4 a  = *(const float4*)&As[kk][ty*4];
            float4 bv = *(const float4*)&Bs[kk][tx*4];
            float av[4] = {a.x, a.y, a.z, a.w};
            float bw[4] = {bv.x, bv.y, bv.z, bv.w};
            #pragma unroll
            for (int i2 = 0; i2 < 4; i2++)
                #pragma unroll
                for (int j2 = 0; j2 < 4; j2++)
                    acc[i2][j2] = fmaf(av[i2], bw[j2], acc[i2][j2]);
        }
        __syncthreads();
    }
    float alpha = alphap[0];
    #pragma unroll
    for (int i2 = 0; i2 < 4; i2++) {
        int row = m0 + ty*4 + i2;
        #pragma unroll
        for (int j2 = 0; j2 < 4; j2++) {
            int col = n0 + tx*4 + j2;
            if (col < N) {
                float v = acc[i2][j2] + bias[col];
                v = (v >= 0.f) ? v : alpha * v;
                C[(size_t)row * N + col] = v;
            }
        }
    }
}

/* enc2 fused: h = prelu(h1 @ W_e2 + b_e2) AND Pa = h @ Wa, Pa stored PAIR-MAJOR
   TRANSPOSED: PaP[c2][node] float2 (c2 = channel pair 0..31). fp32-exact. */
__global__ __launch_bounds__(256) void gemm_enc2_pa_kernel(
    const float* __restrict__ A,   /* h1: [6400,96] */
    const float* __restrict__ W,   /* W_e2: [96,96] */
    const float* __restrict__ bias, const float* __restrict__ alphap,
    const float* __restrict__ Wa,  /* Wd1 rows 0..95: [96,64] */
    float* __restrict__ H, float* __restrict__ P)
{
    __shared__ float As[8][64];
    __shared__ float Bs[8][96];
    __shared__ float hs[64][100];   /* h tile, padded */
    __shared__ float ws[96][64];    /* Wa */
    int tid = threadIdx.x;
    int m0 = blockIdx.x * 64;
    int ty = tid >> 4, tx = tid & 15;
    const int K = HIDDIM, N = HIDDIM;
    float acc[4][6] = {};
    for (int k0 = 0; k0 < K; k0 += 8) {
        #pragma unroll
        for (int i = tid; i < 512; i += 256) {
            int m = i >> 3, k = i & 7;
            As[k][m] = A[(size_t)(m0 + m) * K + (k0 + k)];
        }
        #pragma unroll
        for (int i = tid; i < 768; i += 256) {
            int k = i / 96, n = i - k * 96;
            Bs[k][n] = W[(size_t)(k0 + k) * N + n];
        }
        __syncthreads();
        #pragma unroll
        for (int kk = 0; kk < 8; kk++) {
            float4 a = *(const float4*)&As[kk][ty*4];
            float av[4] = {a.x, a.y, a.z, a.w};
            float bw[6];
            #pragma unroll
            for (int j = 0; j < 6; j++) bw[j] = Bs[kk][tx*6 + j];
            #pragma unroll
            for (int i2 = 0; i2 < 4; i2++)
                #pragma unroll
                for (int j2 = 0; j2 < 6; j2++)
                    acc[i2][j2] = fmaf(av[i2], bw[j2], acc[i2][j2]);
        }
        __syncthreads();
    }
    float alpha = alphap[0];
    #pragma unroll
    for (int i2 = 0; i2 < 4; i2++) {
        int row = m0 + ty*4 + i2;
        #pragma unroll
        for (int j2 = 0; j2 < 6; j2++) {
            int col = tx*6 + j2;
            float v = acc[i2][j2] + bias[col];
            v = (v >= 0.f) ? v : alpha * v;
            H[(size_t)row * N + col] = v;
            hs[ty*4 + i2][col] = v;
        }
    }
    for (int i = tid; i < 96*64; i += 256) {
        int k = i >> 6, n = i & 63;
        ws[k][n] = Wa[(size_t)k * 64 + n];
    }
    __syncthreads();
    /* phase 2: Pa tile 64x64 -> stored transposed pair-major */
    {
        int py = tid >> 4, px = tid & 15;
        float pacc[4][4] = {};
        #pragma unroll 4
        for (int k = 0; k < 96; k++) {
            float hv[4];
            #pragma unroll
            for (int i2 = 0; i2 < 4; i2++) hv[i2] = hs[py*4 + i2][k];
            float4 wv = *(const float4*)&ws[k][px*4];
            float wb[4] = {wv.x, wv.y, wv.z, wv.w};
            #pragma unroll
            for (int i2 = 0; i2 < 4; i2++)
                #pragma unroll
                for (int j2 = 0; j2 < 4; j2++)
                    pacc[i2][j2] = fmaf(hv[i2], wb[j2], pacc[i2][j2]);
        }
        float2* P2 = (float2*)P;   /* [32][NROWS] float2 */
        #pragma unroll
        for (int i2 = 0; i2 < 4; i2++) {
            int row = m0 + py*4 + i2;
            #pragma unroll
            for (int j2h = 0; j2h < 2; j2h++) {
                int c2 = px*2 + j2h;   /* channel pair index: cols 4px+2j2h, +1 */
                P2[(size_t)c2 * NROWS + row] =
                    make_float2(pacc[i2][j2h*2], pacc[i2][j2h*2 + 1]);
            }
        }
    }
}

/* ======= fp16 mma.sync persistent decoder: pair pipelines, transposed Pa ======= */
__global__ __launch_bounds__(256, 2)
void decoder_mma_kernel(
    const float* __restrict__ h, const float* __restrict__ Pa,
    const float* __restrict__ Wd1, const float* __restrict__ b1,
    const float* __restrict__ a1p, const float* __restrict__ W2,
    const float* __restrict__ b2, const float* __restrict__ a2p,
    const float* __restrict__ W3, const float* __restrict__ b3p,
    const int* __restrict__ ei, const int* __restrict__ ej,
    float* __restrict__ out)
{
    extern __shared__ char sm[];
    uint32_t smb = smem_u32(sm);
    int tid  = threadIdx.x;
    int wid  = tid >> 5;
    int lane = tid & 31;
    int g    = lane >> 2;
    int t    = lane & 3;
    int pair  = wid & 3;
    int half  = wid >> 2;
    int mblk  = pair * 32;
    int nhalf = half * 32;
    int barid = pair + 1;

    for (int idx = tid; idx < 64*96; idx += 256) {
        int n = idx / 96, k = idx - n * 96;
        int o = n * 104 + k;
        ((__half*)(sm + OF_WBH))[o] = __float2half_rn(Wd1[(96  + k)*64 + n]);
        ((__half*)(sm + OF_WCH))[o] = __float2half_rn(Wd1[(192 + k)*64 + n]);
    }
    for (int idx = tid; idx < 64*64; idx += 256) {
        int n = idx >> 6, k = idx & 63;
        ((__half*)(sm + OF_W2H))[n * 72 + k] = __float2half_rn(W2[k*64 + n]);
    }
    if (tid < 64) {
        ((float*)(sm + OF_B1))[tid] = b1[tid];
        ((float*)(sm + OF_B2))[tid] = b2[tid];
        ((float*)(sm + OF_W3))[tid] = W3[tid];
    }
    float a1 = a1p[0], a2 = a2p[0], b3 = b3p[0];
    __syncthreads();

    uint32_t laneA  = (uint32_t)((lane & 15)*208 + (lane >> 4)*16);
    uint32_t laneB  = (uint32_t)(((lane >> 4)*8 + (lane & 7))*208 + ((lane >> 3) & 1)*16);
    uint32_t laneAz = (uint32_t)((lane & 15)*144 + (lane >> 4)*16);
    uint32_t laneBz = (uint32_t)(((lane >> 4)*8 + (lane & 7))*144 + ((lane >> 3) & 1)*16);

    uint32_t aAbs = smb + OF_ABSH + mblk*208 + laneA;
    uint32_t aMul = smb + OF_MULH + mblk*208 + laneA;
    uint32_t bWbh = smb + OF_WBH + nhalf*208 + laneB;
    uint32_t bWch = smb + OF_WCH + nhalf*208 + laneB;
    uint32_t aZh  = smb + OF_Z1H + mblk*144 + laneAz;
    uint32_t bW2h = smb + OF_W2H + nhalf*144 + laneBz;

    const int* s_ei = (const int*)(sm + OF_EI);
    const int* s_ej = (const int*)(sm + OF_EJ);
    const float2* PaP = (const float2*)Pa;   /* [32][NROWS] float2 */

    for (int work = blockIdx.x; work < NWORK; work += NCTA_DEC) {
        int b  = work / NTILE;
        int tt = work - b * NTILE;
        int e0 = tt * ETD;
        int bN = b * NN;

        /* ---- stage (pair-local): rows rb..rb+15 ---- */
        {
            int rb = mblk + half*16;
            int myidx;
            {
                int e = e0 + rb + (lane & 15); if (e >= NEDGE) e = NEDGE - 1;
                myidx = (lane < 16) ? ei[e] : ej[e];
            }
            if (lane < 16) ((int*)(sm + OF_EI))[rb + lane] = myidx;
            else           ((int*)(sm + OF_EJ))[rb + lane - 16] = myidx;

            #pragma unroll 4
            for (int e = 0; e < 16; e++) {
                int ii = __shfl_sync(0xffffffffu, myidx, e);
                int jj = __shfl_sync(0xffffffffu, myidx, e + 16);
                if (lane < 24) {
                    const float4* hi4 = (const float4*)(h + ((size_t)bN + ii) * 96);
                    const float4* hj4 = (const float4*)(h + ((size_t)bN + jj) * 96);
                    float4 x = hi4[lane];
                    float4 y = hj4[lane];
                    uint2 aw = make_uint2(packh2(fabsf(x.x - y.x), fabsf(x.y - y.y)),
                                          packh2(fabsf(x.z - y.z), fabsf(x.w - y.w)));
                    uint2 mw = make_uint2(packh2(x.x*y.x, x.y*y.y), packh2(x.z*y.z, x.w*y.w));
                    int row = rb + e;
                    *(uint2*)(sm + OF_ABSH + (size_t)row*208 + lane*8) = aw;
                    *(uint2*)(sm + OF_MULH + (size_t)row*208 + lane*8) = mw;
                }
            }
        }
        PBAR(barid);

        /* ---- GEMM1 ---- */
        float acc[2][4][4];
        #pragma unroll
        for (int mt = 0; mt < 2; mt++)
            #pragma unroll
            for (int nt = 0; nt < 4; nt++)
                #pragma unroll
                for (int c = 0; c < 4; c++) acc[mt][nt][c] = 0.f;

        #pragma unroll
        for (int kc = 0; kc < 6; kc++) {
            uint32_t kb = kc * 32;
            uint32_t Aa[2][4], Am[2][4];
            ldsm4(Aa[0], aAbs + kb);
            ldsm4(Aa[1], aAbs + 16*208 + kb);
            ldsm4(Am[0], aMul + kb);
            ldsm4(Am[1], aMul + 16*208 + kb);
            uint32_t Bb[2][4], Bc[2][4];
            #pragma unroll
            for (int p = 0; p < 2; p++) {
                ldsm4(Bb[p], bWbh + p*16*208 + kb);
                ldsm4(Bc[p], bWch + p*16*208 + kb);
            }
            #pragma unroll
            for (int nt = 0; nt < 4; nt++) {
                int p = nt >> 1, q = (nt & 1) * 2;
                #pragma unroll
                for (int mt = 0; mt < 2; mt++) {
                    float* c = acc[mt][nt];
                    mma_f16(c, Aa[mt], Bb[p][q], Bb[p][q+1]);
                    mma_f16(c, Am[mt], Bc[p][q], Bc[p][q+1]);
                }
            }
        }

        /* ---- epilogue 1: z1 = prelu(C1 + (Pa_i+Pa_j) + b1) -> fp16
               Pa gathered from pair-major transposed layout (few lines/instr) ---- */
        {
            const float* sb1 = (const float*)(sm + OF_B1);
            int c2b = (nhalf >> 1) + t;     /* + nt*4 per nt */
            #pragma unroll
            for (int mt = 0; mt < 2; mt++) {
                int r = mblk + mt*16 + g;
                int bi0 = bN + s_ei[r],   bj0 = bN + s_ej[r];
                int bi1 = bN + s_ei[r+8], bj1 = bN + s_ej[r+8];
                #pragma unroll
                for (int nt = 0; nt < 4; nt++) {
                    int c = nhalf + nt*8 + 2*t;
                    const float2* rowp = PaP + (size_t)(c2b + nt*4) * NROWS;
                    float2 A0 = rowp[bi0];
                    float2 B0 = rowp[bj0];
                    float2 A1 = rowp[bi1];
                    float2 B1 = rowp[bj1];
                    float bc0 = sb1[c], bc1 = sb1[c+1];
                    float u00 = acc[mt][nt][0] + A0.x + B0.x + bc0; u00 = (u00 >= 0.f) ? u00 : a1*u00;
                    float u01 = acc[mt][nt][1] + A0.y + B0.y + bc1; u01 = (u01 >= 0.f) ? u01 : a1*u01;
                    float u10 = acc[mt][nt][2] + A1.x + B1.x + bc0; u10 = (u10 >= 0.f) ? u10 : a1*u10;
                    float u11 = acc[mt][nt][3] + A1.y + B1.y + bc1; u11 = (u11 >= 0.f) ? u11 : a1*u11;
                    *(uint32_t*)(sm + OF_Z1H + (size_t)r*144 + c*2)     = packh2(u00, u01);
                    *(uint32_t*)(sm + OF_Z1H + (size_t)(r+8)*144 + c*2) = packh2(u10, u11);
                }
            }
        }
        PBAR(barid);

        /* ---- GEMM2 ---- */
        float acc2[2][4][4];
        #pragma unroll
        for (int mt = 0; mt < 2; mt++)
            #pragma unroll
            for (int nt = 0; nt < 4; nt++)
                #pragma unroll
                for (int c = 0; c < 4; c++) acc2[mt][nt][c] = 0.f;

        #pragma unroll
        for (int kc = 0; kc < 4; kc++) {
            uint32_t kb = kc * 32;
            uint32_t Zh[2][4];
            ldsm4(Zh[0], aZh + kb);
            ldsm4(Zh[1], aZh + 16*144 + kb);
            uint32_t B2[2][4];
            #pragma unroll
            for (int p = 0; p < 2; p++)
                ldsm4(B2[p], bW2h + p*16*144 + kb);
            #pragma unroll
            for (int nt = 0; nt < 4; nt++) {
                int p = nt >> 1, q = (nt & 1) * 2;
                #pragma unroll
                for (int mt = 0; mt < 2; mt++)
                    mma_f16(acc2[mt][nt], Zh[mt], B2[p][q], B2[p][q+1]);
            }
        }

        /* ---- epilogue 2 ---- */
        {
            const float* sb2 = (const float*)(sm + OF_B2);
            const float* sw3 = (const float*)(sm + OF_W3);
            float pr[2][2] = {{0.f,0.f},{0.f,0.f}};
            #pragma unroll
            for (int mt = 0; mt < 2; mt++) {
                #pragma unroll
                for (int nt = 0; nt < 4; nt++) {
                    int c = nhalf + nt*8 + 2*t;
                    float bc0 = sb2[c], bc1 = sb2[c+1];
                    float w0 = sw3[c],  w1 = sw3[c+1];
                    float u00 = acc2[mt][nt][0] + bc0; u00 = (u00 >= 0.f) ? u00 : a2*u00;
                    float u01 = acc2[mt][nt][1] + bc1; u01 = (u01 >= 0.f) ? u01 : a2*u01;
                    float u10 = acc2[mt][nt][2] + bc0; u10 = (u10 >= 0.f) ? u10 : a2*u10;
                    float u11 = acc2[mt][nt][3] + bc1; u11 = (u11 >= 0.f) ? u11 : a2*u11;
                    pr[mt][0] = fmaf(u00, w0, fmaf(u01, w1, pr[mt][0]));
                    pr[mt][1] = fmaf(u10, w0, fmaf(u11, w1, pr[mt][1]));
                }
            }
            #pragma unroll
            for (int mt = 0; mt < 2; mt++) {
                #pragma unroll
                for (int rr = 0; rr < 2; rr++) {
                    pr[mt][rr] += __shfl_xor_sync(0xffffffffu, pr[mt][rr], 1);
                    pr[mt][rr] += __shfl_xor_sync(0xffffffffu, pr[mt][rr], 2);
                }
            }
            if (t == 0) {
                float* red = (float*)(sm + OF_RED);
                #pragma unroll
                for (int mt = 0; mt < 2; mt++) {
                    int r = mblk + mt*16 + g;
                    red[r*2 + half]     = pr[mt][0];
                    red[(r+8)*2 + half] = pr[mt][1];
                }
            }
        }
        PBAR(barid);

        if (half == 0) {
            const float* red = (const float*)(sm + OF_RED);
            int r  = mblk + lane;
            int eg = e0 + r;
            if (eg < NEDGE)
                out[(size_t)b * NEDGE + eg] = red[r*2] + red[r*2 + 1] + b3;
        }
    }
}

/* ======================= host launcher ======================= */
extern "C" void kernel_launch(void* const* d_in, const int* in_sizes, int n_in,
                              void* d_out, int out_size) {
    (void)in_sizes; (void)n_in; (void)out_size;
    const float* nf    = (const float*)d_in[1];
    const float* sc    = (const float*)d_in[2];
    const float* smean = (const float*)d_in[3];
    const float* sstd  = (const float*)d_in[4];
    const float* We1   = (const float*)d_in[5];
    const float* be1   = (const float*)d_in[6];
    const float* ae1   = (const float*)d_in[7];
    const float* We2   = (const float*)d_in[8];
    const float* be2   = (const float*)d_in[9];
    const float* ae2   = (const float*)d_in[10];
    const float* Wd1   = (const float*)d_in[11];
    const float* bd1   = (const float*)d_in[12];
    const float* ad1   = (const float*)d_in[13];
    const float* Wd2   = (const float*)d_in[14];
    const float* bd2   = (const float*)d_in[15];
    const float* ad2   = (const float*)d_in[16];
    const float* Wd3   = (const float*)d_in[17];
    const float* bd3   = (const float*)d_in[18];
    const int*   ei    = (const int*)d_in[19];
    const int*   ej    = (const int*)d_in[20];
    float* out = (float*)d_out;

    float *ph1, *ph, *ppa;
    cudaGetSymbolAddress((void**)&ph1, g_h1);
    cudaGetSymbolAddress((void**)&ph,  g_h);
    cudaGetSymbolAddress((void**)&ppa, g_Pa);

    cudaFuncSetAttribute(decoder_mma_kernel,
                         cudaFuncAttributeMaxDynamicSharedMemorySize, DEC_SMEM);

    reduce_mean_kernel<<<BATCH, 256>>>(sc);
    gemm_enc1_kernel<<<dim3(NROWS/64, 2), 256>>>(nf, sc, smean, sstd, We1, be1, ae1, ph1);
    gemm_enc2_pa_kernel<<<NROWS/64, 256>>>(ph1, We2, be2, ae2, Wd1, ph, ppa);
    decoder_mma_kernel<<<NCTA_DEC, 256, DEC_SMEM>>>(
        ph, ppa, Wd1, bd1, ad1, Wd2, bd2, ad2, Wd3, bd3, ei, ej, out);
}

// round 15
// speedup vs baseline: 1.0589x; 1.0589x over previous
#include <cuda_runtime.h>
#include <cuda_fp16.h>
#include <cstdint>

#define BATCH   16
#define NN      400
#define HIDDIM  96
#define DECDIM  64
#define NEDGE   79800
#define NROWS   (BATCH*NN)      /* 6400 */
#define FEATDIM 408
#define EPSF    1e-8f

#define ETD     128             /* edges per CTA tile (4 pair-slabs of 32) */
#define NTILE   624             /* ceil(79800/128) */
#define NWORK   (NTILE*BATCH)   /* 9984 */
#define NCTA_DEC 296            /* 2 CTAs per SM */

/* strides: k=96 A arrays padded to 104 halves (208B rows, conflict-free ldmatrix
   perm 20*g mod 32); k=64 z array 72 halves (144B, perm 4*g). */
#define AKW   52
#define ZKW   36

/* ---- decoder smem byte offsets (total 110336 B -> 2 CTAs/SM) ---- */
#define OF_ABSH 0               /* 128x104 f16 = 26624 */
#define OF_MULH 26624
#define OF_WBH  53248           /* 64x104 f16 = 13312 */
#define OF_WCH  66560
#define OF_W2H  79872           /* 64x72 f16 = 9216 */
#define OF_B1   89088
#define OF_B2   89344
#define OF_W3   89600
#define OF_Z1H  89856           /* psum_j then z1 (in place): 128x72 f16 */
#define OF_RED  108288          /* 128x2 f32 = 1024 */
#define OF_EI   109312          /* 128 int */
#define OF_EJ   109824
#define DEC_SMEM 110336

/* -------- scratch (device globals; no runtime allocation allowed) -------- */
__device__ float g_inv[BATCH];
__device__ float g_h1[NROWS*HIDDIM];
__device__ float g_h[NROWS*HIDDIM];
__device__ float g_Pa[NROWS*DECDIM];   /* row-major [node][64] (R13 layout) */

/* ======================= helpers ======================= */
__device__ __forceinline__ uint32_t smem_u32(const void* p) {
    uint32_t a;
    asm("{ .reg .u64 t; cvta.to.shared.u64 t, %1; cvt.u32.u64 %0, t; }" : "=r"(a) : "l"(p));
    return a;
}
__device__ __forceinline__ uint32_t packh2(float x0, float x1) {
    __half2 hh = __floats2half2_rn(x0, x1);
    return *reinterpret_cast<uint32_t*>(&hh);
}
__device__ __forceinline__ float2 unpackh2(uint32_t w) {
    __half2 hh = *reinterpret_cast<__half2*>(&w);
    return __half22float2(hh);
}
__device__ __forceinline__ void ldsm4(uint32_t* r, uint32_t a) {
    asm volatile("ldmatrix.sync.aligned.m8n8.x4.shared.b16 {%0,%1,%2,%3}, [%4];"
                 : "=r"(r[0]), "=r"(r[1]), "=r"(r[2]), "=r"(r[3]) : "r"(a));
}
__device__ __forceinline__ void mma_f16(float* c, const uint32_t* a, uint32_t b0, uint32_t b1) {
    asm volatile("mma.sync.aligned.m16n8k16.row.col.f32.f16.f16.f32 "
                 "{%0,%1,%2,%3}, {%4,%5,%6,%7}, {%8,%9}, {%0,%1,%2,%3};"
                 : "+f"(c[0]), "+f"(c[1]), "+f"(c[2]), "+f"(c[3])
                 : "r"(a[0]), "r"(a[1]), "r"(a[2]), "r"(a[3]), "r"(b0), "r"(b1));
}
/* 64-thread pair barrier (named; ids 1..4) */
#define PBAR(id) asm volatile("bar.sync %0, 64;" :: "r"(id) : "memory")

/* ======================= encoder kernels ======================= */
__global__ void reduce_mean_kernel(const float* __restrict__ sc) {
    __shared__ float red[256];
    int b = blockIdx.x;
    const float* p = sc + (size_t)b * NN * NN;
    float s = 0.f;
    for (int i = threadIdx.x; i < NN*NN; i += 256) s += p[i];
    red[threadIdx.x] = s;
    __syncthreads();
    for (int st = 128; st > 0; st >>= 1) {
        if (threadIdx.x < st) red[threadIdx.x] += red[threadIdx.x + st];
        __syncthreads();
    }
    if (threadIdx.x == 0) g_inv[b] = 1.f / fmaxf(red[0] * (1.f/(float)(NN*NN)), EPSF);
}

__global__ __launch_bounds__(256) void gemm_enc1_kernel(
    const float* __restrict__ nf, const float* __restrict__ sc,
    const float* __restrict__ smean, const float* __restrict__ sstd,
    const float* __restrict__ W, const float* __restrict__ bias,
    const float* __restrict__ alphap, float* __restrict__ C)
{
    __shared__ float As[8][64];
    __shared__ float Bs[8][64];
    int tid = threadIdx.x;
    int m0 = blockIdx.x * 64, n0 = blockIdx.y * 64;
    int ty = tid >> 4, tx = tid & 15;
    const int K = FEATDIM, N = HIDDIM;
    float acc[4][4] = {};
    for (int k0 = 0; k0 < K; k0 += 8) {
        #pragma unroll
        for (int i = tid; i < 512; i += 256) {
            int m = i >> 3, k = i & 7;
            int row = m0 + m, c = k0 + k;
            float v;
            if (c < 8) v = (nf[row*8 + c] - smean[c]) / (sstd[c] + EPSF);
            else       v = sc[(size_t)row*NN + (c-8)] * g_inv[row / NN];
            As[k][m] = v;
        }
        #pragma unroll
        for (int i = tid; i < 512; i += 256) {
            int k = i >> 6, n = i & 63;
            Bs[k][n] = (n0 + n < N) ? W[(size_t)(k0 + k) * N + (n0 + n)] : 0.f;
        }
        __syncthreads();
        #pragma unroll
        for (int kk = 0; kk < 8; kk++) {
            float4 a  = *(const float4*)&As[kk][ty*4];
            float4 bv = *(const float4*)&Bs[kk][tx*4];
            float av[4] = {a.x, a.y, a.z, a.w};
            float bw[4] = {bv.x, bv.y, bv.z, bv.w};
            #pragma unroll
            for (int i2 = 0; i2 < 4; i2++)
                #pragma unroll
                for (int j2 = 0; j2 < 4; j2++)
                    acc[i2][j2] = fmaf(av[i2], bw[j2], acc[i2][j2]);
        }
        __syncthreads();
    }
    float alpha = alphap[0];
    #pragma unroll
    for (int i2 = 0; i2 < 4; i2++) {
        int row = m0 + ty*4 + i2;
        #pragma unroll
        for (int j2 = 0; j2 < 4; j2++) {
            int col = n0 + tx*4 + j2;
            if (col < N) {
                float v = acc[i2][j2] + bias[col];
                v = (v >= 0.f) ? v : alpha * v;
                C[(size_t)row * N + col] = v;
            }
        }
    }
}

/* enc2 fused: h = prelu(h1 @ W_e2 + b_e2) AND Pa = h @ Wa (row-major, fp32) */
__global__ __launch_bounds__(256) void gemm_enc2_pa_kernel(
    const float* __restrict__ A, const float* __restrict__ W,
    const float* __restrict__ bias, const float* __restrict__ alphap,
    const float* __restrict__ Wa,
    float* __restrict__ H, float* __restrict__ P)
{
    __shared__ float As[8][64];
    __shared__ float Bs[8][96];
    __shared__ float hs[64][100];
    __shared__ float ws[96][64];
    int tid = threadIdx.x;
    int m0 = blockIdx.x * 64;
    int ty = tid >> 4, tx = tid & 15;
    const int K = HIDDIM, N = HIDDIM;
    float acc[4][6] = {};
    for (int k0 = 0; k0 < K; k0 += 8) {
        #pragma unroll
        for (int i = tid; i < 512; i += 256) {
            int m = i >> 3, k = i & 7;
            As[k][m] = A[(size_t)(m0 + m) * K + (k0 + k)];
        }
        #pragma unroll
        for (int i = tid; i < 768; i += 256) {
            int k = i / 96, n = i - k * 96;
            Bs[k][n] = W[(size_t)(k0 + k) * N + n];
        }
        __syncthreads();
        #pragma unroll
        for (int kk = 0; kk < 8; kk++) {
            float4 a = *(const float4*)&As[kk][ty*4];
            float av[4] = {a.x, a.y, a.z, a.w};
            float bw[6];
            #pragma unroll
            for (int j = 0; j < 6; j++) bw[j] = Bs[kk][tx*6 + j];
            #pragma unroll
            for (int i2 = 0; i2 < 4; i2++)
                #pragma unroll
                for (int j2 = 0; j2 < 6; j2++)
                    acc[i2][j2] = fmaf(av[i2], bw[j2], acc[i2][j2]);
        }
        __syncthreads();
    }
    float alpha = alphap[0];
    #pragma unroll
    for (int i2 = 0; i2 < 4; i2++) {
        int row = m0 + ty*4 + i2;
        #pragma unroll
        for (int j2 = 0; j2 < 6; j2++) {
            int col = tx*6 + j2;
            float v = acc[i2][j2] + bias[col];
            v = (v >= 0.f) ? v : alpha * v;
            H[(size_t)row * N + col] = v;
            hs[ty*4 + i2][col] = v;
        }
    }
    for (int i = tid; i < 96*64; i += 256) {
        int k = i >> 6, n = i & 63;
        ws[k][n] = Wa[(size_t)k * 64 + n];
    }
    __syncthreads();
    {
        int py = tid >> 4, px = tid & 15;
        float pacc[4][4] = {};
        #pragma unroll 4
        for (int k = 0; k < 96; k++) {
            float hv[4];
            #pragma unroll
            for (int i2 = 0; i2 < 4; i2++) hv[i2] = hs[py*4 + i2][k];
            float4 wv = *(const float4*)&ws[k][px*4];
            float wb[4] = {wv.x, wv.y, wv.z, wv.w};
            #pragma unroll
            for (int i2 = 0; i2 < 4; i2++)
                #pragma unroll
                for (int j2 = 0; j2 < 4; j2++)
                    pacc[i2][j2] = fmaf(hv[i2], wb[j2], pacc[i2][j2]);
        }
        #pragma unroll
        for (int i2 = 0; i2 < 4; i2++) {
            int row = m0 + py*4 + i2;
            #pragma unroll
            for (int j2 = 0; j2 < 4; j2++)
                P[(size_t)row * 64 + px*4 + j2] = pacc[i2][j2];
        }
    }
}

/* ======= decoder: R13 pair pipelines + coalesced Pa_j staging ======= */
__global__ __launch_bounds__(256, 2)
void decoder_mma_kernel(
    const float* __restrict__ h, const float* __restrict__ Pa,
    const float* __restrict__ Wd1, const float* __restrict__ b1,
    const float* __restrict__ a1p, const float* __restrict__ W2,
    const float* __restrict__ b2, const float* __restrict__ a2p,
    const float* __restrict__ W3, const float* __restrict__ b3p,
    const int* __restrict__ ei, const int* __restrict__ ej,
    float* __restrict__ out)
{
    extern __shared__ char sm[];
    uint32_t smb = smem_u32(sm);
    int tid  = threadIdx.x;
    int wid  = tid >> 5;
    int lane = tid & 31;
    int g    = lane >> 2;
    int t    = lane & 3;
    int pair  = wid & 3;
    int half  = wid >> 2;
    int mblk  = pair * 32;
    int nhalf = half * 32;
    int barid = pair + 1;

    for (int idx = tid; idx < 64*96; idx += 256) {
        int n = idx / 96, k = idx - n * 96;
        int o = n * 104 + k;
        ((__half*)(sm + OF_WBH))[o] = __float2half_rn(Wd1[(96  + k)*64 + n]);
        ((__half*)(sm + OF_WCH))[o] = __float2half_rn(Wd1[(192 + k)*64 + n]);
    }
    for (int idx = tid; idx < 64*64; idx += 256) {
        int n = idx >> 6, k = idx & 63;
        ((__half*)(sm + OF_W2H))[n * 72 + k] = __float2half_rn(W2[k*64 + n]);
    }
    if (tid < 64) {
        ((float*)(sm + OF_B1))[tid] = b1[tid];
        ((float*)(sm + OF_B2))[tid] = b2[tid];
        ((float*)(sm + OF_W3))[tid] = W3[tid];
    }
    float a1 = a1p[0], a2 = a2p[0], b3 = b3p[0];
    __syncthreads();

    uint32_t laneA  = (uint32_t)((lane & 15)*208 + (lane >> 4)*16);
    uint32_t laneB  = (uint32_t)(((lane >> 4)*8 + (lane & 7))*208 + ((lane >> 3) & 1)*16);
    uint32_t laneAz = (uint32_t)((lane & 15)*144 + (lane >> 4)*16);
    uint32_t laneBz = (uint32_t)(((lane >> 4)*8 + (lane & 7))*144 + ((lane >> 3) & 1)*16);

    uint32_t aAbs = smb + OF_ABSH + mblk*208 + laneA;
    uint32_t aMul = smb + OF_MULH + mblk*208 + laneA;
    uint32_t bWbh = smb + OF_WBH + nhalf*208 + laneB;
    uint32_t bWch = smb + OF_WCH + nhalf*208 + laneB;
    uint32_t aZh  = smb + OF_Z1H + mblk*144 + laneAz;
    uint32_t bW2h = smb + OF_W2H + nhalf*144 + laneBz;

    const int* s_ei = (const int*)(sm + OF_EI);

    for (int work = blockIdx.x; work < NWORK; work += NCTA_DEC) {
        int b  = work / NTILE;
        int tt = work - b * NTILE;
        int e0 = tt * ETD;
        int bN = b * NN;

        /* ---- stage (pair-local): rows rb..rb+15 ---- */
        {
            int rb = mblk + half*16;
            int myidx;
            {
                int e = e0 + rb + (lane & 15); if (e >= NEDGE) e = NEDGE - 1;
                myidx = (lane < 16) ? ei[e] : ej[e];
            }
            if (lane < 16) ((int*)(sm + OF_EI))[rb + lane] = myidx;

            /* h gather: per edge, lanes 0-23 cover the full 384B row */
            #pragma unroll 4
            for (int e = 0; e < 16; e++) {
                int ii = __shfl_sync(0xffffffffu, myidx, e);
                int jj = __shfl_sync(0xffffffffu, myidx, e + 16);
                if (lane < 24) {
                    const float4* hi4 = (const float4*)(h + ((size_t)bN + ii) * 96);
                    const float4* hj4 = (const float4*)(h + ((size_t)bN + jj) * 96);
                    float4 x = hi4[lane];
                    float4 y = hj4[lane];
                    uint2 aw = make_uint2(packh2(fabsf(x.x - y.x), fabsf(x.y - y.y)),
                                          packh2(fabsf(x.z - y.z), fabsf(x.w - y.w)));
                    uint2 mw = make_uint2(packh2(x.x*y.x, x.y*y.y), packh2(x.z*y.z, x.w*y.w));
                    int row = rb + e;
                    *(uint2*)(sm + OF_ABSH + (size_t)row*208 + lane*8) = aw;
                    *(uint2*)(sm + OF_MULH + (size_t)row*208 + lane*8) = mw;
                }
            }

            /* Pa_j staging (coalesced, fp16 into Z1 region, no reductions):
               2 edges per iter; half-warp per row; lane covers 4 consecutive cols */
            #pragma unroll 4
            for (int it = 0; it < 8; it++) {
                int jj = __shfl_sync(0xffffffffu, myidx, 16 + it*2 + (lane >> 4));
                int l  = lane & 15;
                float4 u = *(const float4*)(Pa + ((size_t)bN + jj) * 64 + l*4);
                int row = rb + it*2 + (lane >> 4);
                *(uint2*)(sm + OF_Z1H + (size_t)row*144 + l*8) =
                    make_uint2(packh2(u.x, u.y), packh2(u.z, u.w));
            }
        }
        PBAR(barid);

        /* ---- GEMM1 ---- */
        float acc[2][4][4];
        #pragma unroll
        for (int mt = 0; mt < 2; mt++)
            #pragma unroll
            for (int nt = 0; nt < 4; nt++)
                #pragma unroll
                for (int c = 0; c < 4; c++) acc[mt][nt][c] = 0.f;

        #pragma unroll
        for (int kc = 0; kc < 6; kc++) {
            uint32_t kb = kc * 32;
            uint32_t Aa[2][4], Am[2][4];
            ldsm4(Aa[0], aAbs + kb);
            ldsm4(Aa[1], aAbs + 16*208 + kb);
            ldsm4(Am[0], aMul + kb);
            ldsm4(Am[1], aMul + 16*208 + kb);
            uint32_t Bb[2][4], Bc[2][4];
            #pragma unroll
            for (int p = 0; p < 2; p++) {
                ldsm4(Bb[p], bWbh + p*16*208 + kb);
                ldsm4(Bc[p], bWch + p*16*208 + kb);
            }
            #pragma unroll
            for (int nt = 0; nt < 4; nt++) {
                int p = nt >> 1, q = (nt & 1) * 2;
                #pragma unroll
                for (int mt = 0; mt < 2; mt++) {
                    float* c = acc[mt][nt];
                    mma_f16(c, Aa[mt], Bb[p][q], Bb[p][q+1]);
                    mma_f16(c, Am[mt], Bc[p][q], Bc[p][q+1]);
                }
            }
        }

        /* ---- epilogue 1: z1 = prelu(C1 + Pa_i(LDG, broadcast-cheap)
                                        + psum_j(smem) + b1) -> fp16 in place ---- */
        {
            const float* sb1 = (const float*)(sm + OF_B1);
            #pragma unroll
            for (int mt = 0; mt < 2; mt++) {
                int r = mblk + mt*16 + g;
                const float* pi0 = Pa + ((size_t)bN + s_ei[r]) * 64;
                const float* pi1 = Pa + ((size_t)bN + s_ei[r+8]) * 64;
                #pragma unroll
                for (int nt = 0; nt < 4; nt++) {
                    int c = nhalf + nt*8 + 2*t;
                    float2 A0 = *(const float2*)(pi0 + c);
                    float2 A1 = *(const float2*)(pi1 + c);
                    float2 J0 = unpackh2(*(uint32_t*)(sm + OF_Z1H + (size_t)r*144 + c*2));
                    float2 J1 = unpackh2(*(uint32_t*)(sm + OF_Z1H + (size_t)(r+8)*144 + c*2));
                    float bc0 = sb1[c], bc1 = sb1[c+1];
                    float u00 = acc[mt][nt][0] + A0.x + J0.x + bc0; u00 = (u00 >= 0.f) ? u00 : a1*u00;
                    float u01 = acc[mt][nt][1] + A0.y + J0.y + bc1; u01 = (u01 >= 0.f) ? u01 : a1*u01;
                    float u10 = acc[mt][nt][2] + A1.x + J1.x + bc0; u10 = (u10 >= 0.f) ? u10 : a1*u10;
                    float u11 = acc[mt][nt][3] + A1.y + J1.y + bc1; u11 = (u11 >= 0.f) ? u11 : a1*u11;
                    *(uint32_t*)(sm + OF_Z1H + (size_t)r*144 + c*2)     = packh2(u00, u01);
                    *(uint32_t*)(sm + OF_Z1H + (size_t)(r+8)*144 + c*2) = packh2(u10, u11);
                }
            }
        }
        PBAR(barid);

        /* ---- GEMM2 ---- */
        float acc2[2][4][4];
        #pragma unroll
        for (int mt = 0; mt < 2; mt++)
            #pragma unroll
            for (int nt = 0; nt < 4; nt++)
                #pragma unroll
                for (int c = 0; c < 4; c++) acc2[mt][nt][c] = 0.f;

        #pragma unroll
        for (int kc = 0; kc < 4; kc++) {
            uint32_t kb = kc * 32;
            uint32_t Zh[2][4];
            ldsm4(Zh[0], aZh + kb);
            ldsm4(Zh[1], aZh + 16*144 + kb);
            uint32_t B2[2][4];
            #pragma unroll
            for (int p = 0; p < 2; p++)
                ldsm4(B2[p], bW2h + p*16*144 + kb);
            #pragma unroll
            for (int nt = 0; nt < 4; nt++) {
                int p = nt >> 1, q = (nt & 1) * 2;
                #pragma unroll
                for (int mt = 0; mt < 2; mt++)
                    mma_f16(acc2[mt][nt], Zh[mt], B2[p][q], B2[p][q+1]);
            }
        }

        /* ---- epilogue 2 ---- */
        {
            const float* sb2 = (const float*)(sm + OF_B2);
            const float* sw3 = (const float*)(sm + OF_W3);
            float pr[2][2] = {{0.f,0.f},{0.f,0.f}};
            #pragma unroll
            for (int mt = 0; mt < 2; mt++) {
                #pragma unroll
                for (int nt = 0; nt < 4; nt++) {
                    int c = nhalf + nt*8 + 2*t;
                    float bc0 = sb2[c], bc1 = sb2[c+1];
                    float w0 = sw3[c],  w1 = sw3[c+1];
                    float u00 = acc2[mt][nt][0] + bc0; u00 = (u00 >= 0.f) ? u00 : a2*u00;
                    float u01 = acc2[mt][nt][1] + bc1; u01 = (u01 >= 0.f) ? u01 : a2*u01;
                    float u10 = acc2[mt][nt][2] + bc0; u10 = (u10 >= 0.f) ? u10 : a2*u10;
                    float u11 = acc2[mt][nt][3] + bc1; u11 = (u11 >= 0.f) ? u11 : a2*u11;
                    pr[mt][0] = fmaf(u00, w0, fmaf(u01, w1, pr[mt][0]));
                    pr[mt][1] = fmaf(u10, w0, fmaf(u11, w1, pr[mt][1]));
                }
            }
            #pragma unroll
            for (int mt = 0; mt < 2; mt++) {
                #pragma unroll
                for (int rr = 0; rr < 2; rr++) {
                    pr[mt][rr] += __shfl_xor_sync(0xffffffffu, pr[mt][rr], 1);
                    pr[mt][rr] += __shfl_xor_sync(0xffffffffu, pr[mt][rr], 2);
                }
            }
            if (t == 0) {
                float* red = (float*)(sm + OF_RED);
                #pragma unroll
                for (int mt = 0; mt < 2; mt++) {
                    int r = mblk + mt*16 + g;
                    red[r*2 + half]     = pr[mt][0];
                    red[(r+8)*2 + half] = pr[mt][1];
                }
            }
        }
        PBAR(barid);

        if (half == 0) {
            const float* red = (const float*)(sm + OF_RED);
            int r  = mblk + lane;
            int eg = e0 + r;
            if (eg < NEDGE)
                out[(size_t)b * NEDGE + eg] = red[r*2] + red[r*2 + 1] + b3;
        }
    }
}

/* ======================= host launcher ======================= */
extern "C" void kernel_launch(void* const* d_in, const int* in_sizes, int n_in,
                              void* d_out, int out_size) {
    (void)in_sizes; (void)n_in; (void)out_size;
    const float* nf    = (const float*)d_in[1];
    const float* sc    = (const float*)d_in[2];
    const float* smean = (const float*)d_in[3];
    const float* sstd  = (const float*)d_in[4];
    const float* We1   = (const float*)d_in[5];
    const float* be1   = (const float*)d_in[6];
    const float* ae1   = (const float*)d_in[7];
    const float* We2   = (const float*)d_in[8];
    const float* be2   = (const float*)d_in[9];
    const float* ae2   = (const float*)d_in[10];
    const float* Wd1   = (const float*)d_in[11];
    const float* bd1   = (const float*)d_in[12];
    const float* ad1   = (const float*)d_in[13];
    const float* Wd2   = (const float*)d_in[14];
    const float* bd2   = (const float*)d_in[15];
    const float* ad2   = (const float*)d_in[16];
    const float* Wd3   = (const float*)d_in[17];
    const float* bd3   = (const float*)d_in[18];
    const int*   ei    = (const int*)d_in[19];
    const int*   ej    = (const int*)d_in[20];
    float* out = (float*)d_out;

    float *ph1, *ph, *ppa;
    cudaGetSymbolAddress((void**)&ph1, g_h1);
    cudaGetSymbolAddress((void**)&ph,  g_h);
    cudaGetSymbolAddress((void**)&ppa, g_Pa);

    cudaFuncSetAttribute(decoder_mma_kernel,
                         cudaFuncAttributeMaxDynamicSharedMemorySize, DEC_SMEM);

    reduce_mean_kernel<<<BATCH, 256>>>(sc);
    gemm_enc1_kernel<<<dim3(NROWS/64, 2), 256>>>(nf, sc, smean, sstd, We1, be1, ae1, ph1);
    gemm_enc2_pa_kernel<<<NROWS/64, 256>>>(ph1, We2, be2, ae2, Wd1, ph, ppa);
    decoder_mma_kernel<<<NCTA_DEC, 256, DEC_SMEM>>>(
        ph, ppa, Wd1, bd1, ad1, Wd2, bd2, ad2, Wd3, bd3, ei, ej, out);
}

// round 16
// speedup vs baseline: 1.2816x; 1.2103x over previous
#include <cuda_runtime.h>
#include <cuda_fp16.h>
#include <cstdint>

#define BATCH   16
#define NN      400
#define HIDDIM  96
#define DECDIM  64
#define NEDGE   79800
#define NROWS   (BATCH*NN)      /* 6400 */
#define FEATDIM 408
#define EPSF    1e-8f

#define ETD     128             /* edges per CTA tile (4 pair-slabs of 32) */
#define NTILE   624             /* ceil(79800/128) */
#define NWORK   (NTILE*BATCH)   /* 9984 */
#define NCTA_DEC 296            /* 2 CTAs per SM */

/* strides: k=96 A arrays padded to 104 halves (208B rows, conflict-free ldmatrix
   perm 20*g mod 32); k=64 z array 72 halves (144B, perm 4*g). */
#define AKW   52
#define ZKW   36

/* ---- decoder smem byte offsets (total 110336 B -> 2 CTAs/SM) ---- */
#define OF_ABSH 0               /* 128x104 f16 = 26624 */
#define OF_MULH 26624
#define OF_WBH  53248           /* 64x104 f16 = 13312 */
#define OF_WCH  66560
#define OF_W2H  79872           /* 64x72 f16 = 9216 */
#define OF_B1   89088
#define OF_B2   89344
#define OF_W3   89600
#define OF_Z1H  89856           /* psum_j then z1 (in place): 128x72 f16 */
#define OF_RED  108288          /* 128x2 f32 = 1024 */
#define OF_EI   109312          /* 128 int */
#define OF_EJ   109824
#define DEC_SMEM 110336

/* -------- scratch (device globals; no runtime allocation allowed) -------- */
__device__ float  g_inv[BATCH];
__device__ float  g_h1[NROWS*HIDDIM];
__device__ __half g_hH[NROWS*HIDDIM];    /* h in fp16 (decoder's only consumer) */
__device__ float  g_Pa[NROWS*DECDIM];    /* row-major [node][64], fp32-exact */

/* ======================= helpers ======================= */
__device__ __forceinline__ uint32_t smem_u32(const void* p) {
    uint32_t a;
    asm("{ .reg .u64 t; cvta.to.shared.u64 t, %1; cvt.u32.u64 %0, t; }" : "=r"(a) : "l"(p));
    return a;
}
__device__ __forceinline__ uint32_t packh2(float x0, float x1) {
    __half2 hh = __floats2half2_rn(x0, x1);
    return *reinterpret_cast<uint32_t*>(&hh);
}
__device__ __forceinline__ float2 unpackh2(uint32_t w) {
    __half2 hh = *reinterpret_cast<__half2*>(&w);
    return __half22float2(hh);
}
__device__ __forceinline__ void ldsm4(uint32_t* r, uint32_t a) {
    asm volatile("ldmatrix.sync.aligned.m8n8.x4.shared.b16 {%0,%1,%2,%3}, [%4];"
                 : "=r"(r[0]), "=r"(r[1]), "=r"(r[2]), "=r"(r[3]) : "r"(a));
}
__device__ __forceinline__ void mma_f16(float* c, const uint32_t* a, uint32_t b0, uint32_t b1) {
    asm volatile("mma.sync.aligned.m16n8k16.row.col.f32.f16.f16.f32 "
                 "{%0,%1,%2,%3}, {%4,%5,%6,%7}, {%8,%9}, {%0,%1,%2,%3};"
                 : "+f"(c[0]), "+f"(c[1]), "+f"(c[2]), "+f"(c[3])
                 : "r"(a[0]), "r"(a[1]), "r"(a[2]), "r"(a[3]), "r"(b0), "r"(b1));
}
/* 64-thread pair barrier (named; ids 1..4) */
#define PBAR(id) asm volatile("bar.sync %0, 64;" :: "r"(id) : "memory")

/* ======================= encoder kernels ======================= */
__global__ void reduce_mean_kernel(const float* __restrict__ sc) {
    __shared__ float red[256];
    int b = blockIdx.x;
    const float* p = sc + (size_t)b * NN * NN;
    float s = 0.f;
    for (int i = threadIdx.x; i < NN*NN; i += 256) s += p[i];
    red[threadIdx.x] = s;
    __syncthreads();
    for (int st = 128; st > 0; st >>= 1) {
        if (threadIdx.x < st) red[threadIdx.x] += red[threadIdx.x + st];
        __syncthreads();
    }
    if (threadIdx.x == 0) g_inv[b] = 1.f / fmaxf(red[0] * (1.f/(float)(NN*NN)), EPSF);
}

__global__ __launch_bounds__(256) void gemm_enc1_kernel(
    const float* __restrict__ nf, const float* __restrict__ sc,
    const float* __restrict__ smean, const float* __restrict__ sstd,
    const float* __restrict__ W, const float* __restrict__ bias,
    const float* __restrict__ alphap, float* __restrict__ C)
{
    __shared__ float As[8][64];
    __shared__ float Bs[8][64];
    int tid = threadIdx.x;
    int m0 = blockIdx.x * 64, n0 = blockIdx.y * 64;
    int ty = tid >> 4, tx = tid & 15;
    const int K = FEATDIM, N = HIDDIM;
    float acc[4][4] = {};
    for (int k0 = 0; k0 < K; k0 += 8) {
        #pragma unroll
        for (int i = tid; i < 512; i += 256) {
            int m = i >> 3, k = i & 7;
            int row = m0 + m, c = k0 + k;
            float v;
            if (c < 8) v = (nf[row*8 + c] - smean[c]) / (sstd[c] + EPSF);
            else       v = sc[(size_t)row*NN + (c-8)] * g_inv[row / NN];
            As[k][m] = v;
        }
        #pragma unroll
        for (int i = tid; i < 512; i += 256) {
            int k = i >> 6, n = i & 63;
            Bs[k][n] = (n0 + n < N) ? W[(size_t)(k0 + k) * N + (n0 + n)] : 0.f;
        }
        __syncthreads();
        #pragma unroll
        for (int kk = 0; kk < 8; kk++) {
            float4 a  = *(const float4*)&As[kk][ty*4];
            float4 bv = *(const float4*)&Bs[kk][tx*4];
            float av[4] = {a.x, a.y, a.z, a.w};
            float bw[4] = {bv.x, bv.y, bv.z, bv.w};
            #pragma unroll
            for (int i2 = 0; i2 < 4; i2++)
                #pragma unroll
                for (int j2 = 0; j2 < 4; j2++)
                    acc[i2][j2] = fmaf(av[i2], bw[j2], acc[i2][j2]);
        }
        __syncthreads();
    }
    float alpha = alphap[0];
    #pragma unroll
    for (int i2 = 0; i2 < 4; i2++) {
        int row = m0 + ty*4 + i2;
        #pragma unroll
        for (int j2 = 0; j2 < 4; j2++) {
            int col = n0 + tx*4 + j2;
            if (col < N) {
                float v = acc[i2][j2] + bias[col];
                v = (v >= 0.f) ? v : alpha * v;
                C[(size_t)row * N + col] = v;
            }
        }
    }
}

/* enc2 fused: h (fp16 out) = prelu(h1 @ W_e2 + b_e2), Pa = h @ Wa (fp32-exact) */
__global__ __launch_bounds__(256) void gemm_enc2_pa_kernel(
    const float* __restrict__ A, const float* __restrict__ W,
    const float* __restrict__ bias, const float* __restrict__ alphap,
    const float* __restrict__ Wa,
    __half* __restrict__ H, float* __restrict__ P)
{
    __shared__ float As[8][64];
    __shared__ float Bs[8][96];
    __shared__ float hs[64][100];
    __shared__ float ws[96][64];
    int tid = threadIdx.x;
    int m0 = blockIdx.x * 64;
    int ty = tid >> 4, tx = tid & 15;
    const int K = HIDDIM, N = HIDDIM;
    float acc[4][6] = {};
    for (int k0 = 0; k0 < K; k0 += 8) {
        #pragma unroll
        for (int i = tid; i < 512; i += 256) {
            int m = i >> 3, k = i & 7;
            As[k][m] = A[(size_t)(m0 + m) * K + (k0 + k)];
        }
        #pragma unroll
        for (int i = tid; i < 768; i += 256) {
            int k = i / 96, n = i - k * 96;
            Bs[k][n] = W[(size_t)(k0 + k) * N + n];
        }
        __syncthreads();
        #pragma unroll
        for (int kk = 0; kk < 8; kk++) {
            float4 a = *(const float4*)&As[kk][ty*4];
            float av[4] = {a.x, a.y, a.z, a.w};
            float bw[6];
            #pragma unroll
            for (int j = 0; j < 6; j++) bw[j] = Bs[kk][tx*6 + j];
            #pragma unroll
            for (int i2 = 0; i2 < 4; i2++)
                #pragma unroll
                for (int j2 = 0; j2 < 6; j2++)
                    acc[i2][j2] = fmaf(av[i2], bw[j2], acc[i2][j2]);
        }
        __syncthreads();
    }
    float alpha = alphap[0];
    #pragma unroll
    for (int i2 = 0; i2 < 4; i2++) {
        int row = m0 + ty*4 + i2;
        float vv[6];
        #pragma unroll
        for (int j2 = 0; j2 < 6; j2++) {
            int col = tx*6 + j2;
            float v = acc[i2][j2] + bias[col];
            v = (v >= 0.f) ? v : alpha * v;
            vv[j2] = v;
            hs[ty*4 + i2][col] = v;
        }
        uint32_t* Hrow = (uint32_t*)(H + (size_t)row * 96);
        Hrow[tx*3 + 0] = packh2(vv[0], vv[1]);
        Hrow[tx*3 + 1] = packh2(vv[2], vv[3]);
        Hrow[tx*3 + 2] = packh2(vv[4], vv[5]);
    }
    for (int i = tid; i < 96*64; i += 256) {
        int k = i >> 6, n = i & 63;
        ws[k][n] = Wa[(size_t)k * 64 + n];
    }
    __syncthreads();
    {
        int py = tid >> 4, px = tid & 15;
        float pacc[4][4] = {};
        #pragma unroll 4
        for (int k = 0; k < 96; k++) {
            float hv[4];
            #pragma unroll
            for (int i2 = 0; i2 < 4; i2++) hv[i2] = hs[py*4 + i2][k];
            float4 wv = *(const float4*)&ws[k][px*4];
            float wb[4] = {wv.x, wv.y, wv.z, wv.w};
            #pragma unroll
            for (int i2 = 0; i2 < 4; i2++)
                #pragma unroll
                for (int j2 = 0; j2 < 4; j2++)
                    pacc[i2][j2] = fmaf(hv[i2], wb[j2], pacc[i2][j2]);
        }
        #pragma unroll
        for (int i2 = 0; i2 < 4; i2++) {
            int row = m0 + py*4 + i2;
            #pragma unroll
            for (int j2 = 0; j2 < 4; j2++)
                P[(size_t)row * 64 + px*4 + j2] = pacc[i2][j2];
        }
    }
}

/* ======= decoder: R15 pair pipelines + fp16 h + staged Pa_j ======= */
__global__ __launch_bounds__(256, 2)
void decoder_mma_kernel(
    const __half* __restrict__ hH, const float* __restrict__ Pa,
    const float* __restrict__ Wd1, const float* __restrict__ b1,
    const float* __restrict__ a1p, const float* __restrict__ W2,
    const float* __restrict__ b2, const float* __restrict__ a2p,
    const float* __restrict__ W3, const float* __restrict__ b3p,
    const int* __restrict__ ei, const int* __restrict__ ej,
    float* __restrict__ out)
{
    extern __shared__ char sm[];
    uint32_t smb = smem_u32(sm);
    int tid  = threadIdx.x;
    int wid  = tid >> 5;
    int lane = tid & 31;
    int g    = lane >> 2;
    int t    = lane & 3;
    int pair  = wid & 3;
    int half  = wid >> 2;
    int mblk  = pair * 32;
    int nhalf = half * 32;
    int barid = pair + 1;

    for (int idx = tid; idx < 64*96; idx += 256) {
        int n = idx / 96, k = idx - n * 96;
        int o = n * 104 + k;
        ((__half*)(sm + OF_WBH))[o] = __float2half_rn(Wd1[(96  + k)*64 + n]);
        ((__half*)(sm + OF_WCH))[o] = __float2half_rn(Wd1[(192 + k)*64 + n]);
    }
    for (int idx = tid; idx < 64*64; idx += 256) {
        int n = idx >> 6, k = idx & 63;
        ((__half*)(sm + OF_W2H))[n * 72 + k] = __float2half_rn(W2[k*64 + n]);
    }
    if (tid < 64) {
        ((float*)(sm + OF_B1))[tid] = b1[tid];
        ((float*)(sm + OF_B2))[tid] = b2[tid];
        ((float*)(sm + OF_W3))[tid] = W3[tid];
    }
    float a1 = a1p[0], a2 = a2p[0], b3 = b3p[0];
    __syncthreads();

    uint32_t laneA  = (uint32_t)((lane & 15)*208 + (lane >> 4)*16);
    uint32_t laneB  = (uint32_t)(((lane >> 4)*8 + (lane & 7))*208 + ((lane >> 3) & 1)*16);
    uint32_t laneAz = (uint32_t)((lane & 15)*144 + (lane >> 4)*16);
    uint32_t laneBz = (uint32_t)(((lane >> 4)*8 + (lane & 7))*144 + ((lane >> 3) & 1)*16);

    uint32_t aAbs = smb + OF_ABSH + mblk*208 + laneA;
    uint32_t aMul = smb + OF_MULH + mblk*208 + laneA;
    uint32_t bWbh = smb + OF_WBH + nhalf*208 + laneB;
    uint32_t bWch = smb + OF_WCH + nhalf*208 + laneB;
    uint32_t aZh  = smb + OF_Z1H + mblk*144 + laneAz;
    uint32_t bW2h = smb + OF_W2H + nhalf*144 + laneBz;

    const int* s_ei = (const int*)(sm + OF_EI);
    const uint4* hb = (const uint4*)hH;   /* 12 uint4 per 96-half row */

    for (int work = blockIdx.x; work < NWORK; work += NCTA_DEC) {
        int b  = work / NTILE;
        int tt = work - b * NTILE;
        int e0 = tt * ETD;
        int bN = b * NN;

        /* ---- stage (pair-local): rows rb..rb+15 ---- */
        {
            int rb = mblk + half*16;
            int myidx;
            {
                int e = e0 + rb + (lane & 15); if (e >= NEDGE) e = NEDGE - 1;
                myidx = (lane < 16) ? ei[e] : ej[e];
            }
            if (lane < 16) ((int*)(sm + OF_EI))[rb + lane] = myidx;

            /* h gather (fp16): 2 edges per iteration, lanes 0-11 / 16-27 */
            #pragma unroll 4
            for (int it = 0; it < 8; it++) {
                int e_loc = it*2 + (lane >> 4);
                int ii = __shfl_sync(0xffffffffu, myidx, e_loc);
                int jj = __shfl_sync(0xffffffffu, myidx, e_loc + 16);
                int l = lane & 15;
                if (l < 12) {
                    uint4 x = hb[(size_t)(bN + ii) * 12 + l];
                    uint4 y = hb[(size_t)(bN + jj) * 12 + l];
                    uint4 aw, mw;
                    const __half2* xp = (const __half2*)&x;
                    const __half2* yp = (const __half2*)&y;
                    __half2* ap = (__half2*)&aw;
                    __half2* mp = (__half2*)&mw;
                    #pragma unroll
                    for (int q = 0; q < 4; q++) {
                        ap[q] = __habs2(__hsub2(xp[q], yp[q]));
                        mp[q] = __hmul2(xp[q], yp[q]);
                    }
                    int row = rb + e_loc;
                    *(uint4*)(sm + OF_ABSH + (size_t)row*208 + l*16) = aw;
                    *(uint4*)(sm + OF_MULH + (size_t)row*208 + l*16) = mw;
                }
            }

            /* Pa_j staging (coalesced, fp16 into Z1 region) */
            #pragma unroll 4
            for (int it = 0; it < 8; it++) {
                int jj = __shfl_sync(0xffffffffu, myidx, 16 + it*2 + (lane >> 4));
                int l  = lane & 15;
                float4 u = *(const float4*)(Pa + ((size_t)bN + jj) * 64 + l*4);
                int row = rb + it*2 + (lane >> 4);
                *(uint2*)(sm + OF_Z1H + (size_t)row*144 + l*8) =
                    make_uint2(packh2(u.x, u.y), packh2(u.z, u.w));
            }
        }
        PBAR(barid);

        /* ---- GEMM1 ---- */
        float acc[2][4][4];
        #pragma unroll
        for (int mt = 0; mt < 2; mt++)
            #pragma unroll
            for (int nt = 0; nt < 4; nt++)
                #pragma unroll
                for (int c = 0; c < 4; c++) acc[mt][nt][c] = 0.f;

        #pragma unroll
        for (int kc = 0; kc < 6; kc++) {
            uint32_t kb = kc * 32;
            uint32_t Aa[2][4], Am[2][4];
            ldsm4(Aa[0], aAbs + kb);
            ldsm4(Aa[1], aAbs + 16*208 + kb);
            ldsm4(Am[0], aMul + kb);
            ldsm4(Am[1], aMul + 16*208 + kb);
            uint32_t Bb[2][4], Bc[2][4];
            #pragma unroll
            for (int p = 0; p < 2; p++) {
                ldsm4(Bb[p], bWbh + p*16*208 + kb);
                ldsm4(Bc[p], bWch + p*16*208 + kb);
            }
            #pragma unroll
            for (int nt = 0; nt < 4; nt++) {
                int p = nt >> 1, q = (nt & 1) * 2;
                #pragma unroll
                for (int mt = 0; mt < 2; mt++) {
                    float* c = acc[mt][nt];
                    mma_f16(c, Aa[mt], Bb[p][q], Bb[p][q+1]);
                    mma_f16(c, Am[mt], Bc[p][q], Bc[p][q+1]);
                }
            }
        }

        /* ---- epilogue 1: z1 = prelu(C1 + Pa_i(LDG) + psum_j(smem) + b1) -> fp16 ---- */
        {
            const float* sb1 = (const float*)(sm + OF_B1);
            #pragma unroll
            for (int mt = 0; mt < 2; mt++) {
                int r = mblk + mt*16 + g;
                const float* pi0 = Pa + ((size_t)bN + s_ei[r]) * 64;
                const float* pi1 = Pa + ((size_t)bN + s_ei[r+8]) * 64;
                #pragma unroll
                for (int nt = 0; nt < 4; nt++) {
                    int c = nhalf + nt*8 + 2*t;
                    float2 A0 = *(const float2*)(pi0 + c);
                    float2 A1 = *(const float2*)(pi1 + c);
                    float2 J0 = unpackh2(*(uint32_t*)(sm + OF_Z1H + (size_t)r*144 + c*2));
                    float2 J1 = unpackh2(*(uint32_t*)(sm + OF_Z1H + (size_t)(r+8)*144 + c*2));
                    float bc0 = sb1[c], bc1 = sb1[c+1];
                    float u00 = acc[mt][nt][0] + A0.x + J0.x + bc0; u00 = (u00 >= 0.f) ? u00 : a1*u00;
                    float u01 = acc[mt][nt][1] + A0.y + J0.y + bc1; u01 = (u01 >= 0.f) ? u01 : a1*u01;
                    float u10 = acc[mt][nt][2] + A1.x + J1.x + bc0; u10 = (u10 >= 0.f) ? u10 : a1*u10;
                    float u11 = acc[mt][nt][3] + A1.y + J1.y + bc1; u11 = (u11 >= 0.f) ? u11 : a1*u11;
                    *(uint32_t*)(sm + OF_Z1H + (size_t)r*144 + c*2)     = packh2(u00, u01);
                    *(uint32_t*)(sm + OF_Z1H + (size_t)(r+8)*144 + c*2) = packh2(u10, u11);
                }
            }
        }
        PBAR(barid);

        /* ---- GEMM2 ---- */
        float acc2[2][4][4];
        #pragma unroll
        for (int mt = 0; mt < 2; mt++)
            #pragma unroll
            for (int nt = 0; nt < 4; nt++)
                #pragma unroll
                for (int c = 0; c < 4; c++) acc2[mt][nt][c] = 0.f;

        #pragma unroll
        for (int kc = 0; kc < 4; kc++) {
            uint32_t kb = kc * 32;
            uint32_t Zh[2][4];
            ldsm4(Zh[0], aZh + kb);
            ldsm4(Zh[1], aZh + 16*144 + kb);
            uint32_t B2[2][4];
            #pragma unroll
            for (int p = 0; p < 2; p++)
                ldsm4(B2[p], bW2h + p*16*144 + kb);
            #pragma unroll
            for (int nt = 0; nt < 4; nt++) {
                int p = nt >> 1, q = (nt & 1) * 2;
                #pragma unroll
                for (int mt = 0; mt < 2; mt++)
                    mma_f16(acc2[mt][nt], Zh[mt], B2[p][q], B2[p][q+1]);
            }
        }

        /* ---- epilogue 2 ---- */
        {
            const float* sb2 = (const float*)(sm + OF_B2);
            const float* sw3 = (const float*)(sm + OF_W3);
            float pr[2][2] = {{0.f,0.f},{0.f,0.f}};
            #pragma unroll
            for (int mt = 0; mt < 2; mt++) {
                #pragma unroll
                for (int nt = 0; nt < 4; nt++) {
                    int c = nhalf + nt*8 + 2*t;
                    float bc0 = sb2[c], bc1 = sb2[c+1];
                    float w0 = sw3[c],  w1 = sw3[c+1];
                    float u00 = acc2[mt][nt][0] + bc0; u00 = (u00 >= 0.f) ? u00 : a2*u00;
                    float u01 = acc2[mt][nt][1] + bc1; u01 = (u01 >= 0.f) ? u01 : a2*u01;
                    float u10 = acc2[mt][nt][2] + bc0; u10 = (u10 >= 0.f) ? u10 : a2*u10;
                    float u11 = acc2[mt][nt][3] + bc1; u11 = (u11 >= 0.f) ? u11 : a2*u11;
                    pr[mt][0] = fmaf(u00, w0, fmaf(u01, w1, pr[mt][0]));
                    pr[mt][1] = fmaf(u10, w0, fmaf(u11, w1, pr[mt][1]));
                }
            }
            #pragma unroll
            for (int mt = 0; mt < 2; mt++) {
                #pragma unroll
                for (int rr = 0; rr < 2; rr++) {
                    pr[mt][rr] += __shfl_xor_sync(0xffffffffu, pr[mt][rr], 1);
                    pr[mt][rr] += __shfl_xor_sync(0xffffffffu, pr[mt][rr], 2);
                }
            }
            if (t == 0) {
                float* red = (float*)(sm + OF_RED);
                #pragma unroll
                for (int mt = 0; mt < 2; mt++) {
                    int r = mblk + mt*16 + g;
                    red[r*2 + half]     = pr[mt][0];
                    red[(r+8)*2 + half] = pr[mt][1];
                }
            }
        }
        PBAR(barid);

        if (half == 0) {
            const float* red = (const float*)(sm + OF_RED);
            int r  = mblk + lane;
            int eg = e0 + r;
            if (eg < NEDGE)
                out[(size_t)b * NEDGE + eg] = red[r*2] + red[r*2 + 1] + b3;
        }
    }
}

/* ======================= host launcher ======================= */
extern "C" void kernel_launch(void* const* d_in, const int* in_sizes, int n_in,
                              void* d_out, int out_size) {
    (void)in_sizes; (void)n_in; (void)out_size;
    const float* nf    = (const float*)d_in[1];
    const float* sc    = (const float*)d_in[2];
    const float* smean = (const float*)d_in[3];
    const float* sstd  = (const float*)d_in[4];
    const float* We1   = (const float*)d_in[5];
    const float* be1   = (const float*)d_in[6];
    const float* ae1   = (const float*)d_in[7];
    const float* We2   = (const float*)d_in[8];
    const float* be2   = (const float*)d_in[9];
    const float* ae2   = (const float*)d_in[10];
    const float* Wd1   = (const float*)d_in[11];
    const float* bd1   = (const float*)d_in[12];
    const float* ad1   = (const float*)d_in[13];
    const float* Wd2   = (const float*)d_in[14];
    const float* bd2   = (const float*)d_in[15];
    const float* ad2   = (const float*)d_in[16];
    const float* Wd3   = (const float*)d_in[17];
    const float* bd3   = (const float*)d_in[18];
    const int*   ei    = (const int*)d_in[19];
    const int*   ej    = (const int*)d_in[20];
    float* out = (float*)d_out;

    float *ph1, *ppa;
    __half* phH;
    cudaGetSymbolAddress((void**)&ph1, g_h1);
    cudaGetSymbolAddress((void**)&phH, g_hH);
    cudaGetSymbolAddress((void**)&ppa, g_Pa);

    cudaFuncSetAttribute(decoder_mma_kernel,
                         cudaFuncAttributeMaxDynamicSharedMemorySize, DEC_SMEM);

    reduce_mean_kernel<<<BATCH, 256>>>(sc);
    gemm_enc1_kernel<<<dim3(NROWS/64, 2), 256>>>(nf, sc, smean, sstd, We1, be1, ae1, ph1);
    gemm_enc2_pa_kernel<<<NROWS/64, 256>>>(ph1, We2, be2, ae2, Wd1, phH, ppa);
    decoder_mma_kernel<<<NCTA_DEC, 256, DEC_SMEM>>>(
        phH, ppa, Wd1, bd1, ad1, Wd2, bd2, ad2, Wd3, bd3, ei, ej, out);
}

// round 17
// speedup vs baseline: 1.3093x; 1.0216x over previous
#include <cuda_runtime.h>
#include <cuda_fp16.h>
#include <cstdint>

#define BATCH   16
#define NN      400
#define HIDDIM  96
#define DECDIM  64
#define NEDGE   79800
#define NROWS   (BATCH*NN)      /* 6400 */
#define FEATDIM 408
#define EPSF    1e-8f

#define ETD     128             /* edges per CTA tile (4 pair-slabs of 32) */
#define NTILE   624             /* ceil(79800/128) */
#define NWORK   (NTILE*BATCH)   /* 9984 */
#define NCTA_DEC 296            /* 2 CTAs per SM */

#define AKW   52
#define ZKW   36

/* ---- decoder smem byte offsets (total 110336 B -> 2 CTAs/SM) ---- */
#define OF_ABSH 0               /* 128x104 f16 = 26624 */
#define OF_MULH 26624
#define OF_WBH  53248           /* 64x104 f16 = 13312 */
#define OF_WCH  66560
#define OF_W2H  79872           /* 64x72 f16 = 9216 */
#define OF_B1   89088           /* b1 packed half2: 32 words */
#define OF_B2   89344
#define OF_W3   89600
#define OF_Z1H  89856           /* psum_j then z1 (in place): 128x72 f16 */
#define OF_RED  108288
#define OF_EI   109312
#define OF_EJ   109824
#define DEC_SMEM 110336

/* -------- scratch (device globals; no runtime allocation allowed) -------- */
__device__ float  g_inv[BATCH];
__device__ float  g_h1[NROWS*HIDDIM];
__device__ __half g_hH[NROWS*HIDDIM];
__device__ float  g_Pa[NROWS*DECDIM];

/* ======================= helpers ======================= */
__device__ __forceinline__ uint32_t smem_u32(const void* p) {
    uint32_t a;
    asm("{ .reg .u64 t; cvta.to.shared.u64 t, %1; cvt.u32.u64 %0, t; }" : "=r"(a) : "l"(p));
    return a;
}
__device__ __forceinline__ uint32_t packh2(float x0, float x1) {
    __half2 hh = __floats2half2_rn(x0, x1);
    return *reinterpret_cast<uint32_t*>(&hh);
}
__device__ __forceinline__ __half2 u2h2(uint32_t w) { return *reinterpret_cast<__half2*>(&w); }
__device__ __forceinline__ uint32_t h2u2(__half2 h) { return *reinterpret_cast<uint32_t*>(&h); }
__device__ __forceinline__ void ldsm4(uint32_t* r, uint32_t a) {
    asm volatile("ldmatrix.sync.aligned.m8n8.x4.shared.b16 {%0,%1,%2,%3}, [%4];"
                 : "=r"(r[0]), "=r"(r[1]), "=r"(r[2]), "=r"(r[3]) : "r"(a));
}
__device__ __forceinline__ void mma_f16(float* c, const uint32_t* a, uint32_t b0, uint32_t b1) {
    asm volatile("mma.sync.aligned.m16n8k16.row.col.f32.f16.f16.f32 "
                 "{%0,%1,%2,%3}, {%4,%5,%6,%7}, {%8,%9}, {%0,%1,%2,%3};"
                 : "+f"(c[0]), "+f"(c[1]), "+f"(c[2]), "+f"(c[3])
                 : "r"(a[0]), "r"(a[1]), "r"(a[2]), "r"(a[3]), "r"(b0), "r"(b1));
}
#define PBAR(id) asm volatile("bar.sync %0, 64;" :: "r"(id) : "memory")

/* ======================= encoder kernels ======================= */
__global__ void reduce_mean_kernel(const float* __restrict__ sc) {
    __shared__ float red[256];
    int b = blockIdx.x;
    const float* p = sc + (size_t)b * NN * NN;
    float s = 0.f;
    for (int i = threadIdx.x; i < NN*NN; i += 256) s += p[i];
    red[threadIdx.x] = s;
    __syncthreads();
    for (int st = 128; st > 0; st >>= 1) {
        if (threadIdx.x < st) red[threadIdx.x] += red[threadIdx.x + st];
        __syncthreads();
    }
    if (threadIdx.x == 0) g_inv[b] = 1.f / fmaxf(red[0] * (1.f/(float)(NN*NN)), EPSF);
}

__global__ __launch_bounds__(256) void gemm_enc1_kernel(
    const float* __restrict__ nf, const float* __restrict__ sc,
    const float* __restrict__ smean, const float* __restrict__ sstd,
    const float* __restrict__ W, const float* __restrict__ bias,
    const float* __restrict__ alphap, float* __restrict__ C)
{
    __shared__ float As[8][64];
    __shared__ float Bs[8][64];
    int tid = threadIdx.x;
    int m0 = blockIdx.x * 64, n0 = blockIdx.y * 64;
    int ty = tid >> 4, tx = tid & 15;
    const int K = FEATDIM, N = HIDDIM;
    float acc[4][4] = {};
    for (int k0 = 0; k0 < K; k0 += 8) {
        #pragma unroll
        for (int i = tid; i < 512; i += 256) {
            int m = i >> 3, k = i & 7;
            int row = m0 + m, c = k0 + k;
            float v;
            if (c < 8) v = (nf[row*8 + c] - smean[c]) / (sstd[c] + EPSF);
            else       v = sc[(size_t)row*NN + (c-8)] * g_inv[row / NN];
            As[k][m] = v;
        }
        #pragma unroll
        for (int i = tid; i < 512; i += 256) {
            int k = i >> 6, n = i & 63;
            Bs[k][n] = (n0 + n < N) ? W[(size_t)(k0 + k) * N + (n0 + n)] : 0.f;
        }
        __syncthreads();
        #pragma unroll
        for (int kk = 0; kk < 8; kk++) {
            float4 a  = *(const float4*)&As[kk][ty*4];
            float4 bv = *(const float4*)&Bs[kk][tx*4];
            float av[4] = {a.x, a.y, a.z, a.w};
            float bw[4] = {bv.x, bv.y, bv.z, bv.w};
            #pragma unroll
            for (int i2 = 0; i2 < 4; i2++)
                #pragma unroll
                for (int j2 = 0; j2 < 4; j2++)
                    acc[i2][j2] = fmaf(av[i2], bw[j2], acc[i2][j2]);
        }
        __syncthreads();
    }
    float alpha = alphap[0];
    #pragma unroll
    for (int i2 = 0; i2 < 4; i2++) {
        int row = m0 + ty*4 + i2;
        #pragma unroll
        for (int j2 = 0; j2 < 4; j2++) {
            int col = n0 + tx*4 + j2;
            if (col < N) {
                float v = acc[i2][j2] + bias[col];
                v = (v >= 0.f) ? v : alpha * v;
                C[(size_t)row * N + col] = v;
            }
        }
    }
}

/* enc2 fused: h (fp16 out) = prelu(h1 @ W_e2 + b_e2), Pa = h @ Wa (fp32-exact) */
__global__ __launch_bounds__(256) void gemm_enc2_pa_kernel(
    const float* __restrict__ A, const float* __restrict__ W,
    const float* __restrict__ bias, const float* __restrict__ alphap,
    const float* __restrict__ Wa,
    __half* __restrict__ H, float* __restrict__ P)
{
    __shared__ float As[8][64];
    __shared__ float Bs[8][96];
    __shared__ float hs[64][100];
    __shared__ float ws[96][64];
    int tid = threadIdx.x;
    int m0 = blockIdx.x * 64;
    int ty = tid >> 4, tx = tid & 15;
    const int K = HIDDIM, N = HIDDIM;
    float acc[4][6] = {};
    for (int k0 = 0; k0 < K; k0 += 8) {
        #pragma unroll
        for (int i = tid; i < 512; i += 256) {
            int m = i >> 3, k = i & 7;
            As[k][m] = A[(size_t)(m0 + m) * K + (k0 + k)];
        }
        #pragma unroll
        for (int i = tid; i < 768; i += 256) {
            int k = i / 96, n = i - k * 96;
            Bs[k][n] = W[(size_t)(k0 + k) * N + n];
        }
        __syncthreads();
        #pragma unroll
        for (int kk = 0; kk < 8; kk++) {
            float4 a = *(const float4*)&As[kk][ty*4];
            float av[4] = {a.x, a.y, a.z, a.w};
            float bw[6];
            #pragma unroll
            for (int j = 0; j < 6; j++) bw[j] = Bs[kk][tx*6 + j];
            #pragma unroll
            for (int i2 = 0; i2 < 4; i2++)
                #pragma unroll
                for (int j2 = 0; j2 < 6; j2++)
                    acc[i2][j2] = fmaf(av[i2], bw[j2], acc[i2][j2]);
        }
        __syncthreads();
    }
    float alpha = alphap[0];
    #pragma unroll
    for (int i2 = 0; i2 < 4; i2++) {
        int row = m0 + ty*4 + i2;
        float vv[6];
        #pragma unroll
        for (int j2 = 0; j2 < 6; j2++) {
            int col = tx*6 + j2;
            float v = acc[i2][j2] + bias[col];
            v = (v >= 0.f) ? v : alpha * v;
            vv[j2] = v;
            hs[ty*4 + i2][col] = v;
        }
        uint32_t* Hrow = (uint32_t*)(H + (size_t)row * 96);
        Hrow[tx*3 + 0] = packh2(vv[0], vv[1]);
        Hrow[tx*3 + 1] = packh2(vv[2], vv[3]);
        Hrow[tx*3 + 2] = packh2(vv[4], vv[5]);
    }
    for (int i = tid; i < 96*64; i += 256) {
        int k = i >> 6, n = i & 63;
        ws[k][n] = Wa[(size_t)k * 64 + n];
    }
    __syncthreads();
    {
        int py = tid >> 4, px = tid & 15;
        float pacc[4][4] = {};
        #pragma unroll 4
        for (int k = 0; k < 96; k++) {
            float hv[4];
            #pragma unroll
            for (int i2 = 0; i2 < 4; i2++) hv[i2] = hs[py*4 + i2][k];
            float4 wv = *(const float4*)&ws[k][px*4];
            float wb[4] = {wv.x, wv.y, wv.z, wv.w};
            #pragma unroll
            for (int i2 = 0; i2 < 4; i2++)
                #pragma unroll
                for (int j2 = 0; j2 < 4; j2++)
                    pacc[i2][j2] = fmaf(hv[i2], wb[j2], pacc[i2][j2]);
        }
        #pragma unroll
        for (int i2 = 0; i2 < 4; i2++) {
            int row = m0 + py*4 + i2;
            #pragma unroll
            for (int j2 = 0; j2 < 4; j2++)
                P[(size_t)row * 64 + px*4 + j2] = pacc[i2][j2];
        }
    }
}

/* ======= decoder: fp16 h + staged Pa_j + half2 epilogue + batched loads ======= */
__global__ __launch_bounds__(256, 2)
void decoder_mma_kernel(
    const __half* __restrict__ hH, const float* __restrict__ Pa,
    const float* __restrict__ Wd1, const float* __restrict__ b1,
    const float* __restrict__ a1p, const float* __restrict__ W2,
    const float* __restrict__ b2, const float* __restrict__ a2p,
    const float* __restrict__ W3, const float* __restrict__ b3p,
    const int* __restrict__ ei, const int* __restrict__ ej,
    float* __restrict__ out)
{
    extern __shared__ char sm[];
    uint32_t smb = smem_u32(sm);
    int tid  = threadIdx.x;
    int wid  = tid >> 5;
    int lane = tid & 31;
    int g    = lane >> 2;
    int t    = lane & 3;
    int pair  = wid & 3;
    int half  = wid >> 2;
    int mblk  = pair * 32;
    int nhalf = half * 32;
    int barid = pair + 1;

    for (int idx = tid; idx < 64*96; idx += 256) {
        int n = idx / 96, k = idx - n * 96;
        int o = n * 104 + k;
        ((__half*)(sm + OF_WBH))[o] = __float2half_rn(Wd1[(96  + k)*64 + n]);
        ((__half*)(sm + OF_WCH))[o] = __float2half_rn(Wd1[(192 + k)*64 + n]);
    }
    for (int idx = tid; idx < 64*64; idx += 256) {
        int n = idx >> 6, k = idx & 63;
        ((__half*)(sm + OF_W2H))[n * 72 + k] = __float2half_rn(W2[k*64 + n]);
    }
    if (tid < 32) ((uint32_t*)(sm + OF_B1))[tid] = packh2(b1[2*tid], b1[2*tid+1]);
    if (tid < 64) {
        ((float*)(sm + OF_B2))[tid] = b2[tid];
        ((float*)(sm + OF_W3))[tid] = W3[tid];
    }
    float a1 = a1p[0], a2 = a2p[0], b3 = b3p[0];
    __half2 a1h = __float2half2_rn(a1);
    __half2 zzh = __float2half2_rn(0.f);
    __syncthreads();

    uint32_t laneA  = (uint32_t)((lane & 15)*208 + (lane >> 4)*16);
    uint32_t laneB  = (uint32_t)(((lane >> 4)*8 + (lane & 7))*208 + ((lane >> 3) & 1)*16);
    uint32_t laneAz = (uint32_t)((lane & 15)*144 + (lane >> 4)*16);
    uint32_t laneBz = (uint32_t)(((lane >> 4)*8 + (lane & 7))*144 + ((lane >> 3) & 1)*16);

    uint32_t aAbs = smb + OF_ABSH + mblk*208 + laneA;
    uint32_t aMul = smb + OF_MULH + mblk*208 + laneA;
    uint32_t bWbh = smb + OF_WBH + nhalf*208 + laneB;
    uint32_t bWch = smb + OF_WCH + nhalf*208 + laneB;
    uint32_t aZh  = smb + OF_Z1H + mblk*144 + laneAz;
    uint32_t bW2h = smb + OF_W2H + nhalf*144 + laneBz;

    const int* s_ei = (const int*)(sm + OF_EI);
    const uint4* hb = (const uint4*)hH;

    for (int work = blockIdx.x; work < NWORK; work += NCTA_DEC) {
        int b  = work / NTILE;
        int tt = work - b * NTILE;
        int e0 = tt * ETD;
        int bN = b * NN;

        /* ---- stage (pair-local): merged h + Pa_j loop for MLP ---- */
        {
            int rb = mblk + half*16;
            int myidx;
            {
                int e = e0 + rb + (lane & 15); if (e >= NEDGE) e = NEDGE - 1;
                myidx = (lane < 16) ? ei[e] : ej[e];
            }
            if (lane < 16) ((int*)(sm + OF_EI))[rb + lane] = myidx;

            #pragma unroll 4
            for (int it = 0; it < 8; it++) {
                int e_loc = it*2 + (lane >> 4);
                int ii = __shfl_sync(0xffffffffu, myidx, e_loc);
                int jj = __shfl_sync(0xffffffffu, myidx, e_loc + 16);
                int l = lane & 15;
                int row = rb + e_loc;
                /* Pa_j: all 32 lanes, 2 rows, coalesced float4 */
                float4 u = *(const float4*)(Pa + ((size_t)bN + jj) * 64 + l*4);
                /* h: lanes l<12 per row */
                if (l < 12) {
                    uint4 x = hb[(size_t)(bN + ii) * 12 + l];
                    uint4 y = hb[(size_t)(bN + jj) * 12 + l];
                    uint4 aw, mw;
                    const __half2* xp = (const __half2*)&x;
                    const __half2* yp = (const __half2*)&y;
                    __half2* ap = (__half2*)&aw;
                    __half2* mp = (__half2*)&mw;
                    #pragma unroll
                    for (int q = 0; q < 4; q++) {
                        ap[q] = __habs2(__hsub2(xp[q], yp[q]));
                        mp[q] = __hmul2(xp[q], yp[q]);
                    }
                    *(uint4*)(sm + OF_ABSH + (size_t)row*208 + l*16) = aw;
                    *(uint4*)(sm + OF_MULH + (size_t)row*208 + l*16) = mw;
                }
                *(uint2*)(sm + OF_Z1H + (size_t)row*144 + l*8) =
                    make_uint2(packh2(u.x, u.y), packh2(u.z, u.w));
            }
        }
        PBAR(barid);

        /* ---- GEMM1 ---- */
        float acc[2][4][4];
        #pragma unroll
        for (int mt = 0; mt < 2; mt++)
            #pragma unroll
            for (int nt = 0; nt < 4; nt++)
                #pragma unroll
                for (int c = 0; c < 4; c++) acc[mt][nt][c] = 0.f;

        #pragma unroll
        for (int kc = 0; kc < 6; kc++) {
            uint32_t kb = kc * 32;
            uint32_t Aa[2][4], Am[2][4];
            ldsm4(Aa[0], aAbs + kb);
            ldsm4(Aa[1], aAbs + 16*208 + kb);
            ldsm4(Am[0], aMul + kb);
            ldsm4(Am[1], aMul + 16*208 + kb);
            uint32_t Bb[2][4], Bc[2][4];
            #pragma unroll
            for (int p = 0; p < 2; p++) {
                ldsm4(Bb[p], bWbh + p*16*208 + kb);
                ldsm4(Bc[p], bWch + p*16*208 + kb);
            }
            #pragma unroll
            for (int nt = 0; nt < 4; nt++) {
                int p = nt >> 1, q = (nt & 1) * 2;
                #pragma unroll
                for (int mt = 0; mt < 2; mt++) {
                    float* c = acc[mt][nt];
                    mma_f16(c, Aa[mt], Bb[p][q], Bb[p][q+1]);
                    mma_f16(c, Am[mt], Bc[p][q], Bc[p][q+1]);
                }
            }
        }

        /* ---- epilogue 1 (half2): z1 = prelu(C1 + Pa_i + psum_j + b1) ---- */
        {
            const uint32_t* sb1h = (const uint32_t*)(sm + OF_B1);
            #pragma unroll
            for (int mt = 0; mt < 2; mt++) {
                int r = mblk + mt*16 + g;
                const float* pi0 = Pa + ((size_t)bN + s_ei[r]) * 64;
                const float* pi1 = Pa + ((size_t)bN + s_ei[r+8]) * 64;
                float2 A0[4], A1[4];
                #pragma unroll
                for (int nt = 0; nt < 4; nt++) {
                    int c = nhalf + nt*8 + 2*t;
                    A0[nt] = *(const float2*)(pi0 + c);
                    A1[nt] = *(const float2*)(pi1 + c);
                }
                #pragma unroll
                for (int nt = 0; nt < 4; nt++) {
                    int c = nhalf + nt*8 + 2*t;
                    __half2 bh = u2h2(sb1h[c >> 1]);
                    __half2 J0 = u2h2(*(uint32_t*)(sm + OF_Z1H + (size_t)r*144 + c*2));
                    __half2 J1 = u2h2(*(uint32_t*)(sm + OF_Z1H + (size_t)(r+8)*144 + c*2));
                    __half2 u0 = __hadd2(__hadd2(u2h2(packh2(acc[mt][nt][0], acc[mt][nt][1])),
                                                 u2h2(packh2(A0[nt].x, A0[nt].y))),
                                         __hadd2(J0, bh));
                    __half2 u1 = __hadd2(__hadd2(u2h2(packh2(acc[mt][nt][2], acc[mt][nt][3])),
                                                 u2h2(packh2(A1[nt].x, A1[nt].y))),
                                         __hadd2(J1, bh));
                    u0 = __hfma2(a1h, __hmin2(u0, zzh), __hmax2(u0, zzh));
                    u1 = __hfma2(a1h, __hmin2(u1, zzh), __hmax2(u1, zzh));
                    *(uint32_t*)(sm + OF_Z1H + (size_t)r*144 + c*2)     = h2u2(u0);
                    *(uint32_t*)(sm + OF_Z1H + (size_t)(r+8)*144 + c*2) = h2u2(u1);
                }
            }
        }
        PBAR(barid);

        /* ---- GEMM2 ---- */
        float acc2[2][4][4];
        #pragma unroll
        for (int mt = 0; mt < 2; mt++)
            #pragma unroll
            for (int nt = 0; nt < 4; nt++)
                #pragma unroll
                for (int c = 0; c < 4; c++) acc2[mt][nt][c] = 0.f;

        #pragma unroll
        for (int kc = 0; kc < 4; kc++) {
            uint32_t kb = kc * 32;
            uint32_t Zh[2][4];
            ldsm4(Zh[0], aZh + kb);
            ldsm4(Zh[1], aZh + 16*144 + kb);
            uint32_t B2[2][4];
            #pragma unroll
            for (int p = 0; p < 2; p++)
                ldsm4(B2[p], bW2h + p*16*144 + kb);
            #pragma unroll
            for (int nt = 0; nt < 4; nt++) {
                int p = nt >> 1, q = (nt & 1) * 2;
                #pragma unroll
                for (int mt = 0; mt < 2; mt++)
                    mma_f16(acc2[mt][nt], Zh[mt], B2[p][q], B2[p][q+1]);
            }
        }

        /* ---- epilogue 2 ---- */
        {
            const float* sb2 = (const float*)(sm + OF_B2);
            const float* sw3 = (const float*)(sm + OF_W3);
            float pr[2][2] = {{0.f,0.f},{0.f,0.f}};
            #pragma unroll
            for (int mt = 0; mt < 2; mt++) {
                #pragma unroll
                for (int nt = 0; nt < 4; nt++) {
                    int c = nhalf + nt*8 + 2*t;
                    float bc0 = sb2[c], bc1 = sb2[c+1];
                    float w0 = sw3[c],  w1 = sw3[c+1];
                    float u00 = acc2[mt][nt][0] + bc0; u00 = (u00 >= 0.f) ? u00 : a2*u00;
                    float u01 = acc2[mt][nt][1] + bc1; u01 = (u01 >= 0.f) ? u01 : a2*u01;
                    float u10 = acc2[mt][nt][2] + bc0; u10 = (u10 >= 0.f) ? u10 : a2*u10;
                    float u11 = acc2[mt][nt][3] + bc1; u11 = (u11 >= 0.f) ? u11 : a2*u11;
                    pr[mt][0] = fmaf(u00, w0, fmaf(u01, w1, pr[mt][0]));
                    pr[mt][1] = fmaf(u10, w0, fmaf(u11, w1, pr[mt][1]));
                }
            }
            #pragma unroll
            for (int mt = 0; mt < 2; mt++) {
                #pragma unroll
                for (int rr = 0; rr < 2; rr++) {
                    pr[mt][rr] += __shfl_xor_sync(0xffffffffu, pr[mt][rr], 1);
                    pr[mt][rr] += __shfl_xor_sync(0xffffffffu, pr[mt][rr], 2);
                }
            }
            if (t == 0) {
                float* red = (float*)(sm + OF_RED);
                #pragma unroll
                for (int mt = 0; mt < 2; mt++) {
                    int r = mblk + mt*16 + g;
                    red[r*2 + half]     = pr[mt][0];
                    red[(r+8)*2 + half] = pr[mt][1];
                }
            }
        }
        PBAR(barid);

        if (half == 0) {
            const float* red = (const float*)(sm + OF_RED);
            int r  = mblk + lane;
            int eg = e0 + r;
            if (eg < NEDGE)
                out[(size_t)b * NEDGE + eg] = red[r*2] + red[r*2 + 1] + b3;
        }
    }
}

/* ======================= host launcher ======================= */
extern "C" void kernel_launch(void* const* d_in, const int* in_sizes, int n_in,
                              void* d_out, int out_size) {
    (void)in_sizes; (void)n_in; (void)out_size;
    const float* nf    = (const float*)d_in[1];
    const float* sc    = (const float*)d_in[2];
    const float* smean = (const float*)d_in[3];
    const float* sstd  = (const float*)d_in[4];
    const float* We1   = (const float*)d_in[5];
    const float* be1   = (const float*)d_in[6];
    const float* ae1   = (const float*)d_in[7];
    const float* We2   = (const float*)d_in[8];
    const float* be2   = (const float*)d_in[9];
    const float* ae2   = (const float*)d_in[10];
    const float* Wd1   = (const float*)d_in[11];
    const float* bd1   = (const float*)d_in[12];
    const float* ad1   = (const float*)d_in[13];
    const float* Wd2   = (const float*)d_in[14];
    const float* bd2   = (const float*)d_in[15];
    const float* ad2   = (const float*)d_in[16];
    const float* Wd3   = (const float*)d_in[17];
    const float* bd3   = (const float*)d_in[18];
    const int*   ei    = (const int*)d_in[19];
    const int*   ej    = (const int*)d_in[20];
    float* out = (float*)d_out;

    float *ph1, *ppa;
    __half* phH;
    cudaGetSymbolAddress((void**)&ph1, g_h1);
    cudaGetSymbolAddress((void**)&phH, g_hH);
    cudaGetSymbolAddress((void**)&ppa, g_Pa);

    cudaFuncSetAttribute(decoder_mma_kernel,
                         cudaFuncAttributeMaxDynamicSharedMemorySize, DEC_SMEM);

    reduce_mean_kernel<<<BATCH, 256>>>(sc);
    gemm_enc1_kernel<<<dim3(NROWS/64, 2), 256>>>(nf, sc, smean, sstd, We1, be1, ae1, ph1);
    gemm_enc2_pa_kernel<<<NROWS/64, 256>>>(ph1, We2, be2, ae2, Wd1, phH, ppa);
    decoder_mma_kernel<<<NCTA_DEC, 256, DEC_SMEM>>>(
        phH, ppa, Wd1, bd1, ad1, Wd2, bd2, ad2, Wd3, bd3, ei, ej, out);
}